// round 1
// baseline (speedup 1.0000x reference)
#include <cuda_runtime.h>
#include <math.h>

// Problem constants
constexpr int S  = 1024;
constexpr int Mm = 128;
constexpr int D  = 1024;
constexpr int H  = 16;
constexpr int HD = 64;
constexpr int F  = 2048;
constexpr int L  = 8;
constexpr int TOT = S + 2 * Mm;     // 1280 rows in residual stream
constexpr int KHID = Mm + S;        // 1152 keys for hidden attention

// ---------------- scratch pool (single __device__ global) ----------------
constexpr size_t OFF_CAT  = 0;                          // 1280*1024
constexpr size_t OFF_X    = 1310720;
constexpr size_t OFF_Y    = 2621440;
constexpr size_t OFF_ATTN = 3932160;
constexpr size_t OFF_Q    = 5242880;                    // 16*1024*64
constexpr size_t OFF_QB   = 6291456;                    // 16*128*64
constexpr size_t OFF_QF   = 6422528;
constexpr size_t OFF_K    = 6553600;                    // 16*1280*64
constexpr size_t OFF_V    = 7864320;
constexpr size_t OFF_KF   = 9175040;                    // 16*128*64
constexpr size_t OFF_VF   = 9306112;
constexpr size_t OFF_TQKV = 9437184;                    // 3*1024*1024
constexpr size_t OFF_TSM  = 12582912;                   // 8*128*1024
constexpr size_t OFF_TG   = 13631488;                   // 1280*2048
constexpr size_t OFF_TU   = 16252928;                   // 1280*2048
constexpr size_t OFF_COS  = 18874368;                   // 1280*64
constexpr size_t OFF_SIN  = 18956288;                   // 1280*64
constexpr size_t POOL_SZ  = 19038208;

__device__ float g_pool[POOL_SZ];

// ---------------- rope tables ----------------
__global__ void k_tables(float* cosT, float* sinT) {
    int idx = blockIdx.x * blockDim.x + threadIdx.x;
    if (idx >= 1280 * 64) return;
    int p = idx >> 6;
    int d = idx & 63;
    int i = d & 31;
    double inv = pow(10000.0, -((double)i) / 32.0);
    double ang = (double)p * inv;
    cosT[idx] = (float)cos(ang);
    sinT[idx] = (float)sin(ang);
}

// ---------------- initial residual stream: [embed(ids); beacon; forget] ----------------
__global__ void k_fillcat(float* cat, const int* __restrict__ ids,
                          const float* __restrict__ embed,
                          const float* __restrict__ beacon,
                          const float* __restrict__ forget) {
    int idx = blockIdx.x * blockDim.x + threadIdx.x;
    if (idx >= TOT * D) return;
    int row = idx >> 10;
    int d = idx & 1023;
    float v;
    if (row < S)            v = embed[(size_t)ids[row] * D + d];
    else if (row < S + Mm)  v = beacon[(size_t)(row - S) * D + d];
    else                    v = forget[(size_t)(row - S - Mm) * D + d];
    cat[idx] = v;
}

// ---------------- layer-entry gated output: out[l] = mem*sig(fgt) + bcn*(1-sig(fgt)) ----------------
__global__ void k_outgate(float* __restrict__ out, const float* __restrict__ mem,
                          const float* __restrict__ cat) {
    int idx = blockIdx.x * blockDim.x + threadIdx.x;
    if (idx >= Mm * D) return;
    float bcn = cat[(size_t)S * D + idx];
    float fgt = cat[(size_t)(S + Mm) * D + idx];
    float g = 1.0f / (1.0f + expf(-fgt));
    out[idx] = mem[idx] * g + bcn * (1.0f - g);
}

// ---------------- rmsnorm (one block per row) ----------------
__global__ void k_rms(const float* __restrict__ in, const float* __restrict__ w,
                      float* __restrict__ outp) {
    int row = blockIdx.x;
    const float* r = in + (size_t)row * D;
    float ss = 0.0f;
    for (int i = threadIdx.x; i < D; i += 256) { float v = r[i]; ss = fmaf(v, v, ss); }
    #pragma unroll
    for (int o = 16; o; o >>= 1) ss += __shfl_xor_sync(0xffffffffu, ss, o);
    __shared__ float wsum[8];
    __shared__ float sc;
    if ((threadIdx.x & 31) == 0) wsum[threadIdx.x >> 5] = ss;
    __syncthreads();
    if (threadIdx.x == 0) {
        float tot = 0.0f;
        #pragma unroll
        for (int i = 0; i < 8; i++) tot += wsum[i];
        sc = rsqrtf(tot / (float)D + 1e-5f);
    }
    __syncthreads();
    float scale = sc;
    float* op = outp + (size_t)row * D;
    for (int i = threadIdx.x; i < D; i += 256) op[i] = r[i] * scale * w[i];
}

// ---------------- batched SGEMM: C[z] = A[z] @ B[z] (+C), 64x64 tile, 256 thr, 4x4 micro ----------------
struct GemmArgs {
    const float* A[8];
    const float* B[8];
    float*       C[8];
};

__global__ void __launch_bounds__(256) k_gemm(GemmArgs ga, int Mr, int N, int K, int accFlag) {
    const float* A = ga.A[blockIdx.z];
    const float* B = ga.B[blockIdx.z];
    float*       C = ga.C[blockIdx.z];

    __shared__ __align__(16) float As[16][64];
    __shared__ __align__(16) float Bs[16][64];

    int t  = threadIdx.x;
    int tx = t & 15;
    int ty = t >> 4;
    int m0 = blockIdx.y * 64;
    int n0 = blockIdx.x * 64;

    int am = t >> 2;            // 0..63 (A row within tile)
    int ak = (t & 3) << 2;      // 0,4,8,12
    const float* Aptr = A + (size_t)(m0 + am) * K + ak;

    float acc[4][4];
    #pragma unroll
    for (int i = 0; i < 4; i++)
        #pragma unroll
        for (int j = 0; j < 4; j++) acc[i][j] = 0.0f;

    for (int k0 = 0; k0 < K; k0 += 16) {
        float4 av = *(const float4*)(Aptr + k0);
        As[ak + 0][am] = av.x;
        As[ak + 1][am] = av.y;
        As[ak + 2][am] = av.z;
        As[ak + 3][am] = av.w;
        #pragma unroll
        for (int i = 0; i < 4; i++) {
            int idx = t + i * 256;
            int kk = idx >> 6, nn = idx & 63;
            Bs[kk][nn] = B[(size_t)(k0 + kk) * N + n0 + nn];
        }
        __syncthreads();
        #pragma unroll
        for (int k = 0; k < 16; k++) {
            float4 a = *(const float4*)(&As[k][ty << 2]);
            float4 b = *(const float4*)(&Bs[k][tx << 2]);
            acc[0][0] = fmaf(a.x, b.x, acc[0][0]);
            acc[0][1] = fmaf(a.x, b.y, acc[0][1]);
            acc[0][2] = fmaf(a.x, b.z, acc[0][2]);
            acc[0][3] = fmaf(a.x, b.w, acc[0][3]);
            acc[1][0] = fmaf(a.y, b.x, acc[1][0]);
            acc[1][1] = fmaf(a.y, b.y, acc[1][1]);
            acc[1][2] = fmaf(a.y, b.z, acc[1][2]);
            acc[1][3] = fmaf(a.y, b.w, acc[1][3]);
            acc[2][0] = fmaf(a.z, b.x, acc[2][0]);
            acc[2][1] = fmaf(a.z, b.y, acc[2][1]);
            acc[2][2] = fmaf(a.z, b.z, acc[2][2]);
            acc[2][3] = fmaf(a.z, b.w, acc[2][3]);
            acc[3][0] = fmaf(a.w, b.x, acc[3][0]);
            acc[3][1] = fmaf(a.w, b.y, acc[3][1]);
            acc[3][2] = fmaf(a.w, b.z, acc[3][2]);
            acc[3][3] = fmaf(a.w, b.w, acc[3][3]);
        }
        __syncthreads();
    }

    float* Cp = C + (size_t)(m0 + (ty << 2)) * N + n0 + (tx << 2);
    #pragma unroll
    for (int i = 0; i < 4; i++) {
        float4 v;
        v.x = acc[i][0]; v.y = acc[i][1]; v.z = acc[i][2]; v.w = acc[i][3];
        if (accFlag) {
            float4 old = *(const float4*)(Cp + (size_t)i * N);
            v.x += old.x; v.y += old.y; v.z += old.z; v.w += old.w;
        }
        *(float4*)(Cp + (size_t)i * N) = v;
    }
}

// ---------------- rope + head-major reshape (batched via grid.y) ----------------
struct RsOne {
    const float* src;   // [rows][1024]
    float*       dst;   // [H][dstStride][64]
    int rows;
    int dstStride;
    int dstOff;
    int posBase;        // <0 => no rope
};
struct RsArgs { RsOne e[11]; };

__global__ void k_reshape(RsArgs ra, const float* __restrict__ cosT,
                          const float* __restrict__ sinT) {
    RsOne a = ra.e[blockIdx.y];
    int idx = blockIdx.x * 256 + threadIdx.x;
    if (idx >= a.rows * 1024) return;
    int row = idx >> 10;
    int n = idx & 1023;
    int h = n >> 6;
    int d = n & 63;
    float v = a.src[idx];
    float o;
    if (a.posBase >= 0) {
        int pos = a.posBase + row;
        float partner = (d < 32)
            ? -a.src[(size_t)row * 1024 + h * 64 + d + 32]
            :  a.src[(size_t)row * 1024 + h * 64 + d - 32];
        o = v * cosT[pos * 64 + d] + partner * sinT[pos * 64 + d];
    } else {
        o = v;
    }
    a.dst[((size_t)h * a.dstStride + a.dstOff + row) * 64 + d] = o;
}

// ---------------- flash-style attention ----------------
// 128 threads, 32 queries/block, streaming 32-key tiles, online softmax.
// Keys: segment1 (len1, head stride hs1) then segment2 (len2, head stride hs2).
// Mask: key j visible iff j < P or (j - P) <= query_index.
__global__ void __launch_bounds__(128) k_attn(
    const float* __restrict__ Q, int nq,
    const float* __restrict__ K1, const float* __restrict__ V1, int len1, int hs1,
    const float* __restrict__ K2, const float* __restrict__ V2, int len2, int hs2,
    int P, float* __restrict__ Out)
{
    constexpr int TQ = 32, TK = 32;
    int h  = blockIdx.y;
    int qb = blockIdx.x * TQ;
    int t  = threadIdx.x;
    int r  = t >> 2;           // query row within tile
    int c4 = t & 3;
    int d0 = c4 * 16;

    __shared__ __align__(16) float Ks[TK][64];
    __shared__ __align__(16) float Vs[TK][64];

    const float* Qh = Q + (size_t)h * nq * 64;

    float qreg[16];
    #pragma unroll
    for (int i = 0; i < 16; i += 4) {
        float4 v = *(const float4*)(Qh + (size_t)(qb + r) * 64 + d0 + i);
        qreg[i + 0] = v.x * 0.125f;
        qreg[i + 1] = v.y * 0.125f;
        qreg[i + 2] = v.z * 0.125f;
        qreg[i + 3] = v.w * 0.125f;
    }

    float m = -3.0e38f, lsum = 0.0f;
    float O[16];
    #pragma unroll
    for (int i = 0; i < 16; i++) O[i] = 0.0f;

    int total = len1 + len2;
    int eff = min(total, P + qb + TQ);   // causal early-exit (eff is multiple of 32 here)
    int ntk = (eff + TK - 1) / TK;
    int qi = qb + r;

    for (int kt = 0; kt < ntk; kt++) {
        int j = kt * TK + r;    // this thread loads key row j, dims d0..d0+15
        const float *kp, *vp;
        if (j < len1) {
            kp = K1 + (size_t)h * hs1 + (size_t)j * 64;
            vp = V1 + (size_t)h * hs1 + (size_t)j * 64;
        } else {
            kp = K2 + (size_t)h * hs2 + (size_t)(j - len1) * 64;
            vp = V2 + (size_t)h * hs2 + (size_t)(j - len1) * 64;
        }
        __syncthreads();
        #pragma unroll
        for (int i = 0; i < 16; i += 4) {
            *(float4*)(&Ks[r][d0 + i]) = *(const float4*)(kp + d0 + i);
            *(float4*)(&Vs[r][d0 + i]) = *(const float4*)(vp + d0 + i);
        }
        __syncthreads();

        float s[TK];
        #pragma unroll
        for (int k = 0; k < TK; k++) {
            const float4* kp4 = (const float4*)(&Ks[k][d0]);
            float a = 0.0f;
            #pragma unroll
            for (int i4 = 0; i4 < 4; i4++) {
                float4 kv = kp4[i4];
                a = fmaf(qreg[i4 * 4 + 0], kv.x, a);
                a = fmaf(qreg[i4 * 4 + 1], kv.y, a);
                a = fmaf(qreg[i4 * 4 + 2], kv.z, a);
                a = fmaf(qreg[i4 * 4 + 3], kv.w, a);
            }
            s[k] = a;
        }
        #pragma unroll
        for (int k = 0; k < TK; k++) {
            s[k] += __shfl_xor_sync(0xffffffffu, s[k], 1);
            s[k] += __shfl_xor_sync(0xffffffffu, s[k], 2);
        }
        int jg0 = kt * TK;
        #pragma unroll
        for (int k = 0; k < TK; k++) {
            int jg = jg0 + k;
            bool vis = (jg < P) || (jg - P <= qi);
            if (!vis) s[k] = -3.0e38f;
        }
        float tmax = s[0];
        #pragma unroll
        for (int k = 1; k < TK; k++) tmax = fmaxf(tmax, s[k]);
        float nm = fmaxf(m, tmax);
        float corr = __expf(m - nm);
        lsum *= corr;
        #pragma unroll
        for (int i = 0; i < 16; i++) O[i] *= corr;
        #pragma unroll
        for (int k = 0; k < TK; k++) {
            float p = __expf(s[k] - nm);
            lsum += p;
            const float4* vp4 = (const float4*)(&Vs[k][d0]);
            #pragma unroll
            for (int i4 = 0; i4 < 4; i4++) {
                float4 vv = vp4[i4];
                O[i4 * 4 + 0] = fmaf(p, vv.x, O[i4 * 4 + 0]);
                O[i4 * 4 + 1] = fmaf(p, vv.y, O[i4 * 4 + 1]);
                O[i4 * 4 + 2] = fmaf(p, vv.z, O[i4 * 4 + 2]);
                O[i4 * 4 + 3] = fmaf(p, vv.w, O[i4 * 4 + 3]);
            }
        }
        m = nm;
    }

    float inv = 1.0f / lsum;
    float* op = Out + (size_t)(qb + r) * 1024 + h * 64 + d0;
    #pragma unroll
    for (int i4 = 0; i4 < 4; i4++) {
        float4 v;
        v.x = O[i4 * 4 + 0] * inv;
        v.y = O[i4 * 4 + 1] * inv;
        v.z = O[i4 * 4 + 2] * inv;
        v.w = O[i4 * 4 + 3] * inv;
        *(float4*)(op + i4 * 4) = v;
    }
}

// ---------------- MLP activation: g = silu(g) * u ----------------
__global__ void k_silu(float* __restrict__ g, const float* __restrict__ u) {
    int idx = blockIdx.x * blockDim.x + threadIdx.x;
    if (idx >= TOT * F) return;
    float x = g[idx];
    float s = x / (1.0f + expf(-x));
    g[idx] = s * u[idx];
}

// ---------------- host driver ----------------
extern "C" void kernel_launch(void* const* d_in, const int* in_sizes, int n_in,
                              void* d_out, int out_size) {
    (void)in_sizes; (void)n_in; (void)out_size;

    const int*   ids    = (const int*)  d_in[0];
    const float* memory = (const float*)d_in[1];
    const float* beacon = (const float*)d_in[2];
    const float* forget = (const float*)d_in[3];
    const float* embed  = (const float*)d_in[4];
    const float* ln1    = (const float*)d_in[5];
    const float* ln2    = (const float*)d_in[6];
    const float* Wq     = (const float*)d_in[7];
    const float* Wk     = (const float*)d_in[8];
    const float* Wv     = (const float*)d_in[9];
    const float* Wo     = (const float*)d_in[10];
    const float* mWk    = (const float*)d_in[11];
    const float* mWv    = (const float*)d_in[12];
    const float* bWq    = (const float*)d_in[13];
    const float* bWk    = (const float*)d_in[14];
    const float* bWv    = (const float*)d_in[15];
    const float* fWq    = (const float*)d_in[16];
    const float* fWk    = (const float*)d_in[17];
    const float* fWv    = (const float*)d_in[18];
    const float* Wg     = (const float*)d_in[19];
    const float* Wu     = (const float*)d_in[20];
    const float* Wd     = (const float*)d_in[21];
    float* out = (float*)d_out;

    float* pool = nullptr;
    cudaGetSymbolAddress((void**)&pool, g_pool);

    float* cat  = pool + OFF_CAT;
    float* x    = pool + OFF_X;
    float* y    = pool + OFF_Y;
    float* attn = pool + OFF_ATTN;
    float* qh   = pool + OFF_Q;
    float* qbuf_b = pool + OFF_QB;
    float* qbuf_f = pool + OFF_QF;
    float* kbuf = pool + OFF_K;
    float* vbuf = pool + OFF_V;
    float* kf   = pool + OFF_KF;
    float* vf   = pool + OFF_VF;
    float* tqkv = pool + OFF_TQKV;
    float* tsm  = pool + OFF_TSM;
    float* tg   = pool + OFF_TG;
    float* tu   = pool + OFF_TU;
    float* cosT = pool + OFF_COS;
    float* sinT = pool + OFF_SIN;

    k_tables<<<(1280 * 64 + 255) / 256, 256>>>(cosT, sinT);
    k_fillcat<<<(TOT * D + 255) / 256, 256>>>(cat, ids, embed, beacon, forget);

    const size_t WDD = (size_t)D * D;       // per-layer stride for DxD weights
    const size_t WDF = (size_t)D * F;       // Wg/Wu stride
    const size_t WFD = (size_t)F * D;       // Wd stride
    const size_t MDsz = (size_t)Mm * D;

    for (int l = 0; l < L; l++) {
        const float* mem_l = memory + (size_t)l * MDsz;

        // output for this layer uses INCOMING beacon/forget
        k_outgate<<<(Mm * D + 255) / 256, 256>>>(out + (size_t)l * MDsz, mem_l, cat);

        // rmsnorm ln1
        k_rms<<<TOT, 256>>>(cat, ln1 + (size_t)l * D, x);

        // hidden QKV (batched x3)
        {
            GemmArgs ga = {};
            ga.A[0] = x; ga.A[1] = x; ga.A[2] = x;
            ga.B[0] = Wq + l * WDD; ga.B[1] = Wk + l * WDD; ga.B[2] = Wv + l * WDD;
            ga.C[0] = tqkv; ga.C[1] = tqkv + 1048576; ga.C[2] = tqkv + 2097152;
            k_gemm<<<dim3(16, 16, 3), 256>>>(ga, S, D, D, 0);
        }
        // eight small 128-row projections (batched x8)
        {
            GemmArgs ga = {};
            const float* bx = x + (size_t)S * D;
            const float* fx = x + (size_t)(S + Mm) * D;
            ga.A[0] = mem_l; ga.A[1] = mem_l;
            ga.A[2] = bx; ga.A[3] = bx; ga.A[4] = bx;
            ga.A[5] = fx; ga.A[6] = fx; ga.A[7] = fx;
            ga.B[0] = mWk + l * WDD; ga.B[1] = mWv + l * WDD;
            ga.B[2] = bWq + l * WDD; ga.B[3] = bWk + l * WDD; ga.B[4] = bWv + l * WDD;
            ga.B[5] = fWq + l * WDD; ga.B[6] = fWk + l * WDD; ga.B[7] = fWv + l * WDD;
            for (int z = 0; z < 8; z++) ga.C[z] = tsm + (size_t)z * 131072;
            k_gemm<<<dim3(16, 2, 8), 256>>>(ga, Mm, D, D, 0);
        }
        // rope + reshape to head-major K/V/Q buffers (batched x11)
        {
            RsArgs ra;
            ra.e[0]  = { tqkv,            qh,     S,  1024, 0,    Mm };   // Q hid, pos 128..
            ra.e[1]  = { tqkv + 1048576,  kbuf,   S,  1280, 128,  Mm };   // K hid
            ra.e[2]  = { tqkv + 2097152,  vbuf,   S,  1280, 128,  -1 };   // V hid
            ra.e[3]  = { tsm,             kbuf,   Mm, 1280, 0,    0  };   // mem K, pos 0..
            ra.e[4]  = { tsm + 131072,    vbuf,   Mm, 1280, 0,    -1 };   // mem V
            ra.e[5]  = { tsm + 262144,    qbuf_b, Mm, 128,  0,    KHID }; // beacon Q, pos 1152..
            ra.e[6]  = { tsm + 393216,    kbuf,   Mm, 1280, KHID, KHID }; // beacon K
            ra.e[7]  = { tsm + 524288,    vbuf,   Mm, 1280, KHID, -1 };   // beacon V
            ra.e[8]  = { tsm + 655360,    qbuf_f, Mm, 128,  0,    KHID }; // forget Q
            ra.e[9]  = { tsm + 786432,    kf,     Mm, 128,  0,    KHID }; // forget K
            ra.e[10] = { tsm + 917504,    vf,     Mm, 128,  0,    -1 };   // forget V
            k_reshape<<<dim3(4096, 11), 256>>>(ra, cosT, sinT);
        }
        // attention: hidden, beacon, forget
        k_attn<<<dim3(S / 32, H), 128>>>(qh, S,
                                         kbuf, vbuf, KHID, 1280 * 64,
                                         kf, vf, 0, 128 * 64,
                                         Mm, attn);
        k_attn<<<dim3(Mm / 32, H), 128>>>(qbuf_b, Mm,
                                          kbuf, vbuf, TOT, 1280 * 64,
                                          kf, vf, 0, 128 * 64,
                                          KHID, attn + (size_t)S * D);
        k_attn<<<dim3(Mm / 32, H), 128>>>(qbuf_f, Mm,
                                          kbuf, vbuf, KHID, 1280 * 64,
                                          kf, vf, Mm, 128 * 64,
                                          KHID, attn + (size_t)KHID * D);
        // Wo projection, accumulate into residual
        {
            GemmArgs ga = {};
            ga.A[0] = attn; ga.B[0] = Wo + l * WDD; ga.C[0] = cat;
            k_gemm<<<dim3(16, 20, 1), 256>>>(ga, TOT, D, D, 1);
        }
        // rmsnorm ln2
        k_rms<<<TOT, 256>>>(cat, ln2 + (size_t)l * D, y);
        // MLP: gate & up (batched x2)
        {
            GemmArgs ga = {};
            ga.A[0] = y; ga.A[1] = y;
            ga.B[0] = Wg + l * WDF; ga.B[1] = Wu + l * WDF;
            ga.C[0] = tg; ga.C[1] = tu;
            k_gemm<<<dim3(32, 20, 2), 256>>>(ga, TOT, F, D, 0);
        }
        k_silu<<<(TOT * F + 255) / 256, 256>>>(tg, tu);
        // down projection, accumulate into residual
        {
            GemmArgs ga = {};
            ga.A[0] = tg; ga.B[0] = Wd + l * WFD; ga.C[0] = cat;
            k_gemm<<<dim3(16, 20, 1), 256>>>(ga, TOT, D, F, 1);
        }
    }
}

// round 2
// speedup vs baseline: 1.3620x; 1.3620x over previous
#include <cuda_runtime.h>
#include <cuda_bf16.h>
#include <math.h>

// Problem constants
constexpr int S  = 1024;
constexpr int Mm = 128;
constexpr int D  = 1024;
constexpr int H  = 16;
constexpr int HD = 64;
constexpr int F  = 2048;
constexpr int L  = 8;
constexpr int TOT = S + 2 * Mm;     // 1280 rows in residual stream
constexpr int KHID = Mm + S;        // 1152 keys for hidden attention

// ---------------- scratch pool (single __device__ global) ----------------
constexpr size_t OFF_CAT  = 0;                          // 1280*1024
constexpr size_t OFF_X    = 1310720;
constexpr size_t OFF_Y    = 2621440;
constexpr size_t OFF_ATTN = 3932160;
constexpr size_t OFF_Q    = 5242880;                    // 16*1024*64
constexpr size_t OFF_QB   = 6291456;                    // 16*128*64
constexpr size_t OFF_QF   = 6422528;
constexpr size_t OFF_K    = 6553600;                    // 16*1280*64
constexpr size_t OFF_V    = 7864320;
constexpr size_t OFF_KF   = 9175040;                    // 16*128*64
constexpr size_t OFF_VF   = 9306112;
constexpr size_t OFF_TQKV = 9437184;                    // 3*1024*1024
constexpr size_t OFF_TSM  = 12582912;                   // 8*128*1024
constexpr size_t OFF_TG   = 13631488;                   // 1280*2048
constexpr size_t OFF_TU   = 16252928;                   // 1280*2048
constexpr size_t OFF_COS  = 18874368;                   // 1280*64
constexpr size_t OFF_SIN  = 18956288;                   // 1280*64
constexpr size_t POOL_SZ  = 19038208;

__device__ float g_pool[POOL_SZ];

// ---------------- rope tables ----------------
__global__ void k_tables(float* cosT, float* sinT) {
    int idx = blockIdx.x * blockDim.x + threadIdx.x;
    if (idx >= 1280 * 64) return;
    int p = idx >> 6;
    int d = idx & 63;
    int i = d & 31;
    double inv = pow(10000.0, -((double)i) / 32.0);
    double ang = (double)p * inv;
    cosT[idx] = (float)cos(ang);
    sinT[idx] = (float)sin(ang);
}

// ---------------- initial residual stream ----------------
__global__ void k_fillcat(float* cat, const int* __restrict__ ids,
                          const float* __restrict__ embed,
                          const float* __restrict__ beacon,
                          const float* __restrict__ forget) {
    int idx = blockIdx.x * blockDim.x + threadIdx.x;
    if (idx >= TOT * D) return;
    int row = idx >> 10;
    int d = idx & 1023;
    float v;
    if (row < S)            v = embed[(size_t)ids[row] * D + d];
    else if (row < S + Mm)  v = beacon[(size_t)(row - S) * D + d];
    else                    v = forget[(size_t)(row - S - Mm) * D + d];
    cat[idx] = v;
}

// ---------------- layer-entry gated output ----------------
__global__ void k_outgate(float* __restrict__ out, const float* __restrict__ mem,
                          const float* __restrict__ cat) {
    int idx = blockIdx.x * blockDim.x + threadIdx.x;
    if (idx >= Mm * D) return;
    float bcn = cat[(size_t)S * D + idx];
    float fgt = cat[(size_t)(S + Mm) * D + idx];
    float g = 1.0f / (1.0f + expf(-fgt));
    out[idx] = mem[idx] * g + bcn * (1.0f - g);
}

// ---------------- rmsnorm ----------------
__global__ void k_rms(const float* __restrict__ in, const float* __restrict__ w,
                      float* __restrict__ outp) {
    int row = blockIdx.x;
    const float* r = in + (size_t)row * D;
    float ss = 0.0f;
    for (int i = threadIdx.x; i < D; i += 256) { float v = r[i]; ss = fmaf(v, v, ss); }
    #pragma unroll
    for (int o = 16; o; o >>= 1) ss += __shfl_xor_sync(0xffffffffu, ss, o);
    __shared__ float wsum[8];
    __shared__ float sc;
    if ((threadIdx.x & 31) == 0) wsum[threadIdx.x >> 5] = ss;
    __syncthreads();
    if (threadIdx.x == 0) {
        float tot = 0.0f;
        #pragma unroll
        for (int i = 0; i < 8; i++) tot += wsum[i];
        sc = rsqrtf(tot / (float)D + 1e-5f);
    }
    __syncthreads();
    float scale = sc;
    float* op = outp + (size_t)row * D;
    for (int i = threadIdx.x; i < D; i += 256) op[i] = r[i] * scale * w[i];
}

// =======================================================================
// Tensor-core GEMM: C[z] = A[z] @ B[z] (+C) with fp32 operands split into
// hi/lo bf16 (A*B ~= Ah*Bh + Ah*Bl + Al*Bh), mma.sync m16n8k16, fp32 acc.
// CTA tile 128x128, BK=32, 8 warps (each 64x32), double-buffered smem.
// =======================================================================
struct GemmArgs {
    const float* A[8];
    const float* B[8];
    float*       C[8];
};

__device__ __forceinline__ void mma16816(float* c, const unsigned* a, const unsigned* b) {
    asm volatile(
        "mma.sync.aligned.m16n8k16.row.col.f32.bf16.bf16.f32 "
        "{%0,%1,%2,%3}, {%4,%5,%6,%7}, {%8,%9}, {%0,%1,%2,%3};"
        : "+f"(c[0]), "+f"(c[1]), "+f"(c[2]), "+f"(c[3])
        : "r"(a[0]), "r"(a[1]), "r"(a[2]), "r"(a[3]), "r"(b[0]), "r"(b[1]));
}
__device__ __forceinline__ void ldsm4(unsigned* r, unsigned addr) {
    asm volatile("ldmatrix.sync.aligned.m8n8.x4.shared.b16 {%0,%1,%2,%3}, [%4];"
                 : "=r"(r[0]), "=r"(r[1]), "=r"(r[2]), "=r"(r[3]) : "r"(addr));
}
__device__ __forceinline__ void ldsm2t(unsigned* r, unsigned addr) {
    asm volatile("ldmatrix.sync.aligned.m8n8.x2.trans.shared.b16 {%0,%1}, [%2];"
                 : "=r"(r[0]), "=r"(r[1]) : "r"(addr));
}

// smem element-layout (bf16 units), per stage 4096 elems each array:
//   AsH: s*4096            AsL: 8192 + s*4096
//   BsH: 16384 + s*4096    BsL: 24576 + s*4096
__global__ void __launch_bounds__(256) k_mma(GemmArgs ga, int N, int K, int accFlag) {
    extern __shared__ __nv_bfloat16 sm[];
    const float* A = ga.A[blockIdx.z];
    const float* B = ga.B[blockIdx.z];
    float*       C = ga.C[blockIdx.z];

    const int t  = threadIdx.x;
    const int l  = t & 31;
    const int w  = t >> 5;
    const int wr = w >> 2;          // warp row (0..1) -> 64 M rows
    const int wc = w & 3;           // warp col (0..3) -> 32 N cols
    const int by = blockIdx.y, bx = blockIdx.x;

    const unsigned smem_u32 = (unsigned)__cvta_generic_to_shared(sm);

    // ---- per-lane ldmatrix element offsets (stage-relative) ----
    // A frags: [ks][mt]
    unsigned aOff[2][4];
    {
        int arow = l & 15;
        int achk = l >> 4;
        #pragma unroll
        for (int ks = 0; ks < 2; ks++)
            #pragma unroll
            for (int mt = 0; mt < 4; mt++) {
                int row = wr * 64 + mt * 16 + arow;
                int chunk = ks * 2 + achk;
                aOff[ks][mt] = row * 32 + ((chunk ^ ((row >> 1) & 3)) << 3);
            }
    }
    // B frags: [ks][nt]
    unsigned bOff[2][4];
    {
        int brow = l & 15;
        #pragma unroll
        for (int ks = 0; ks < 2; ks++)
            #pragma unroll
            for (int nt = 0; nt < 4; nt++) {
                int k = ks * 16 + brow;
                bOff[ks][nt] = k * 128 + ((((wc << 2) + nt) ^ (k & 7)) << 3);
            }
    }

    float acc[4][4][4];
    #pragma unroll
    for (int i = 0; i < 4; i++)
        #pragma unroll
        for (int j = 0; j < 4; j++)
            #pragma unroll
            for (int q = 0; q < 4; q++) acc[i][j][q] = 0.0f;

    const int nk = K >> 5;
    float4 ar[4], br[4];

    // ---- global load of tile kt into registers ----
    auto load_tile = [&](int kt) {
        #pragma unroll
        for (int i = 0; i < 4; i++) {
            int f = t + i * 256;
            int row = f >> 3, k4 = (f & 7) << 2;
            ar[i] = *(const float4*)(A + (size_t)(by * 128 + row) * K + kt * 32 + k4);
        }
        #pragma unroll
        for (int i = 0; i < 4; i++) {
            int f = t + i * 256;
            int krow = f >> 5, n4 = (f & 31) << 2;
            br[i] = *(const float4*)(B + (size_t)(kt * 32 + krow) * N + bx * 128 + n4);
        }
    };
    // ---- split + store registers into smem stage s ----
    auto store_tile = [&](int s) {
        int aH = s * 4096, aL = 8192 + s * 4096;
        int bH = 16384 + s * 4096, bL = 24576 + s * 4096;
        #pragma unroll
        for (int i = 0; i < 4; i++) {
            int f = t + i * 256;
            int row = f >> 3, k4 = (f & 7) << 2;
            float4 v = ar[i];
            __nv_bfloat162 h01 = __floats2bfloat162_rn(v.x, v.y);
            __nv_bfloat162 h23 = __floats2bfloat162_rn(v.z, v.w);
            __nv_bfloat162 l01 = __floats2bfloat162_rn(v.x - __bfloat162float(h01.x),
                                                       v.y - __bfloat162float(h01.y));
            __nv_bfloat162 l23 = __floats2bfloat162_rn(v.z - __bfloat162float(h23.x),
                                                       v.w - __bfloat162float(h23.y));
            int e = row * 32 + (((k4 >> 3) ^ ((row >> 1) & 3)) << 3) + (k4 & 7);
            *(__nv_bfloat162*)(sm + aH + e)     = h01;
            *(__nv_bfloat162*)(sm + aH + e + 2) = h23;
            *(__nv_bfloat162*)(sm + aL + e)     = l01;
            *(__nv_bfloat162*)(sm + aL + e + 2) = l23;
        }
        #pragma unroll
        for (int i = 0; i < 4; i++) {
            int f = t + i * 256;
            int k = f >> 5, n4 = (f & 31) << 2;
            float4 v = br[i];
            __nv_bfloat162 h01 = __floats2bfloat162_rn(v.x, v.y);
            __nv_bfloat162 h23 = __floats2bfloat162_rn(v.z, v.w);
            __nv_bfloat162 l01 = __floats2bfloat162_rn(v.x - __bfloat162float(h01.x),
                                                       v.y - __bfloat162float(h01.y));
            __nv_bfloat162 l23 = __floats2bfloat162_rn(v.z - __bfloat162float(h23.x),
                                                       v.w - __bfloat162float(h23.y));
            int e = k * 128 + ((((n4 >> 3)) ^ (k & 7)) << 3) + (n4 & 7);
            *(__nv_bfloat162*)(sm + bH + e)     = h01;
            *(__nv_bfloat162*)(sm + bH + e + 2) = h23;
            *(__nv_bfloat162*)(sm + bL + e)     = l01;
            *(__nv_bfloat162*)(sm + bL + e + 2) = l23;
        }
    };

    load_tile(0);
    store_tile(0);
    __syncthreads();

    for (int kt = 0; kt < nk; kt++) {
        int s = kt & 1;
        bool more = (kt + 1 < nk);
        if (more) load_tile(kt + 1);

        unsigned sAH = smem_u32 + (s * 4096) * 2;
        unsigned sBH = smem_u32 + (16384 + s * 4096) * 2;
        #pragma unroll
        for (int ks = 0; ks < 2; ks++) {
            unsigned aHf[4][4], aLf[4][4], bHf[4][2], bLf[4][2];
            #pragma unroll
            for (int mt = 0; mt < 4; mt++) {
                unsigned ad = sAH + aOff[ks][mt] * 2;
                ldsm4(aHf[mt], ad);
                ldsm4(aLf[mt], ad + 16384);
            }
            #pragma unroll
            for (int nt = 0; nt < 4; nt++) {
                unsigned bd = sBH + bOff[ks][nt] * 2;
                ldsm2t(bHf[nt], bd);
                ldsm2t(bLf[nt], bd + 16384);
            }
            #pragma unroll
            for (int mt = 0; mt < 4; mt++)
                #pragma unroll
                for (int nt = 0; nt < 4; nt++)
                    mma16816(acc[mt][nt], aHf[mt], bHf[nt]);
            #pragma unroll
            for (int mt = 0; mt < 4; mt++)
                #pragma unroll
                for (int nt = 0; nt < 4; nt++) {
                    mma16816(acc[mt][nt], aHf[mt], bLf[nt]);
                    mma16816(acc[mt][nt], aLf[mt], bHf[nt]);
                }
        }
        if (more) { store_tile(s ^ 1); __syncthreads(); }
    }

    // ---- epilogue ----
    int r0 = wr * 64 + (l >> 2);
    int c0 = wc * 32 + (l & 3) * 2;
    #pragma unroll
    for (int mt = 0; mt < 4; mt++) {
        #pragma unroll
        for (int nt = 0; nt < 4; nt++) {
            int row = by * 128 + r0 + mt * 16;
            int col = bx * 128 + c0 + nt * 8;
            float2 v01 = { acc[mt][nt][0], acc[mt][nt][1] };
            float2 v23 = { acc[mt][nt][2], acc[mt][nt][3] };
            float* p0 = C + (size_t)row * N + col;
            float* p1 = C + (size_t)(row + 8) * N + col;
            if (accFlag) {
                float2 o0 = *(const float2*)p0;
                float2 o1 = *(const float2*)p1;
                v01.x += o0.x; v01.y += o0.y;
                v23.x += o1.x; v23.y += o1.y;
            }
            *(float2*)p0 = v01;
            *(float2*)p1 = v23;
        }
    }
}

// ---------------- rope + head-major reshape (batched via grid.y) ----------------
struct RsOne {
    const float* src;
    float*       dst;
    int rows;
    int dstStride;
    int dstOff;
    int posBase;
};
struct RsArgs { RsOne e[11]; };

__global__ void k_reshape(RsArgs ra, const float* __restrict__ cosT,
                          const float* __restrict__ sinT) {
    RsOne a = ra.e[blockIdx.y];
    int idx = blockIdx.x * 256 + threadIdx.x;
    if (idx >= a.rows * 1024) return;
    int row = idx >> 10;
    int n = idx & 1023;
    int h = n >> 6;
    int d = n & 63;
    float v = a.src[idx];
    float o;
    if (a.posBase >= 0) {
        int pos = a.posBase + row;
        float partner = (d < 32)
            ? -a.src[(size_t)row * 1024 + h * 64 + d + 32]
            :  a.src[(size_t)row * 1024 + h * 64 + d - 32];
        o = v * cosT[pos * 64 + d] + partner * sinT[pos * 64 + d];
    } else {
        o = v;
    }
    a.dst[((size_t)h * a.dstStride + a.dstOff + row) * 64 + d] = o;
}

// ---------------- flash-style attention (unchanged) ----------------
__global__ void __launch_bounds__(128) k_attn(
    const float* __restrict__ Q, int nq,
    const float* __restrict__ K1, const float* __restrict__ V1, int len1, int hs1,
    const float* __restrict__ K2, const float* __restrict__ V2, int len2, int hs2,
    int P, float* __restrict__ Out)
{
    constexpr int TQ = 32, TK = 32;
    int h  = blockIdx.y;
    int qb = blockIdx.x * TQ;
    int t  = threadIdx.x;
    int r  = t >> 2;
    int c4 = t & 3;
    int d0 = c4 * 16;

    __shared__ __align__(16) float Ks[TK][64];
    __shared__ __align__(16) float Vs[TK][64];

    const float* Qh = Q + (size_t)h * nq * 64;

    float qreg[16];
    #pragma unroll
    for (int i = 0; i < 16; i += 4) {
        float4 v = *(const float4*)(Qh + (size_t)(qb + r) * 64 + d0 + i);
        qreg[i + 0] = v.x * 0.125f;
        qreg[i + 1] = v.y * 0.125f;
        qreg[i + 2] = v.z * 0.125f;
        qreg[i + 3] = v.w * 0.125f;
    }

    float m = -3.0e38f, lsum = 0.0f;
    float O[16];
    #pragma unroll
    for (int i = 0; i < 16; i++) O[i] = 0.0f;

    int total = len1 + len2;
    int eff = min(total, P + qb + TQ);
    int ntk = (eff + TK - 1) / TK;
    int qi = qb + r;

    for (int kt = 0; kt < ntk; kt++) {
        int j = kt * TK + r;
        const float *kp, *vp;
        if (j < len1) {
            kp = K1 + (size_t)h * hs1 + (size_t)j * 64;
            vp = V1 + (size_t)h * hs1 + (size_t)j * 64;
        } else {
            kp = K2 + (size_t)h * hs2 + (size_t)(j - len1) * 64;
            vp = V2 + (size_t)h * hs2 + (size_t)(j - len1) * 64;
        }
        __syncthreads();
        #pragma unroll
        for (int i = 0; i < 16; i += 4) {
            *(float4*)(&Ks[r][d0 + i]) = *(const float4*)(kp + d0 + i);
            *(float4*)(&Vs[r][d0 + i]) = *(const float4*)(vp + d0 + i);
        }
        __syncthreads();

        float s[TK];
        #pragma unroll
        for (int k = 0; k < TK; k++) {
            const float4* kp4 = (const float4*)(&Ks[k][d0]);
            float a = 0.0f;
            #pragma unroll
            for (int i4 = 0; i4 < 4; i4++) {
                float4 kv = kp4[i4];
                a = fmaf(qreg[i4 * 4 + 0], kv.x, a);
                a = fmaf(qreg[i4 * 4 + 1], kv.y, a);
                a = fmaf(qreg[i4 * 4 + 2], kv.z, a);
                a = fmaf(qreg[i4 * 4 + 3], kv.w, a);
            }
            s[k] = a;
        }
        #pragma unroll
        for (int k = 0; k < TK; k++) {
            s[k] += __shfl_xor_sync(0xffffffffu, s[k], 1);
            s[k] += __shfl_xor_sync(0xffffffffu, s[k], 2);
        }
        int jg0 = kt * TK;
        #pragma unroll
        for (int k = 0; k < TK; k++) {
            int jg = jg0 + k;
            bool vis = (jg < P) || (jg - P <= qi);
            if (!vis) s[k] = -3.0e38f;
        }
        float tmax = s[0];
        #pragma unroll
        for (int k = 1; k < TK; k++) tmax = fmaxf(tmax, s[k]);
        float nm = fmaxf(m, tmax);
        float corr = __expf(m - nm);
        lsum *= corr;
        #pragma unroll
        for (int i = 0; i < 16; i++) O[i] *= corr;
        #pragma unroll
        for (int k = 0; k < TK; k++) {
            float p = __expf(s[k] - nm);
            lsum += p;
            const float4* vp4 = (const float4*)(&Vs[k][d0]);
            #pragma unroll
            for (int i4 = 0; i4 < 4; i4++) {
                float4 vv = vp4[i4];
                O[i4 * 4 + 0] = fmaf(p, vv.x, O[i4 * 4 + 0]);
                O[i4 * 4 + 1] = fmaf(p, vv.y, O[i4 * 4 + 1]);
                O[i4 * 4 + 2] = fmaf(p, vv.z, O[i4 * 4 + 2]);
                O[i4 * 4 + 3] = fmaf(p, vv.w, O[i4 * 4 + 3]);
            }
        }
        m = nm;
    }

    float inv = 1.0f / lsum;
    float* op = Out + (size_t)(qb + r) * 1024 + h * 64 + d0;
    #pragma unroll
    for (int i4 = 0; i4 < 4; i4++) {
        float4 v;
        v.x = O[i4 * 4 + 0] * inv;
        v.y = O[i4 * 4 + 1] * inv;
        v.z = O[i4 * 4 + 2] * inv;
        v.w = O[i4 * 4 + 3] * inv;
        *(float4*)(op + i4 * 4) = v;
    }
}

// ---------------- MLP activation ----------------
__global__ void k_silu(float* __restrict__ g, const float* __restrict__ u) {
    int idx = blockIdx.x * blockDim.x + threadIdx.x;
    if (idx >= TOT * F) return;
    float x = g[idx];
    float s = x / (1.0f + expf(-x));
    g[idx] = s * u[idx];
}

// ---------------- host driver ----------------
extern "C" void kernel_launch(void* const* d_in, const int* in_sizes, int n_in,
                              void* d_out, int out_size) {
    (void)in_sizes; (void)n_in; (void)out_size;

    const int*   ids    = (const int*)  d_in[0];
    const float* memory = (const float*)d_in[1];
    const float* beacon = (const float*)d_in[2];
    const float* forget = (const float*)d_in[3];
    const float* embed  = (const float*)d_in[4];
    const float* ln1    = (const float*)d_in[5];
    const float* ln2    = (const float*)d_in[6];
    const float* Wq     = (const float*)d_in[7];
    const float* Wk     = (const float*)d_in[8];
    const float* Wv     = (const float*)d_in[9];
    const float* Wo     = (const float*)d_in[10];
    const float* mWk    = (const float*)d_in[11];
    const float* mWv    = (const float*)d_in[12];
    const float* bWq    = (const float*)d_in[13];
    const float* bWk    = (const float*)d_in[14];
    const float* bWv    = (const float*)d_in[15];
    const float* fWq    = (const float*)d_in[16];
    const float* fWk    = (const float*)d_in[17];
    const float* fWv    = (const float*)d_in[18];
    const float* Wg     = (const float*)d_in[19];
    const float* Wu     = (const float*)d_in[20];
    const float* Wd     = (const float*)d_in[21];
    float* out = (float*)d_out;

    float* pool = nullptr;
    cudaGetSymbolAddress((void**)&pool, g_pool);

    float* cat  = pool + OFF_CAT;
    float* x    = pool + OFF_X;
    float* y    = pool + OFF_Y;
    float* attn = pool + OFF_ATTN;
    float* qh   = pool + OFF_Q;
    float* qbuf_b = pool + OFF_QB;
    float* qbuf_f = pool + OFF_QF;
    float* kbuf = pool + OFF_K;
    float* vbuf = pool + OFF_V;
    float* kf   = pool + OFF_KF;
    float* vf   = pool + OFF_VF;
    float* tqkv = pool + OFF_TQKV;
    float* tsm  = pool + OFF_TSM;
    float* tg   = pool + OFF_TG;
    float* tu   = pool + OFF_TU;
    float* cosT = pool + OFF_COS;
    float* sinT = pool + OFF_SIN;

    constexpr int SMEM_MMA = 65536;
    cudaFuncSetAttribute(k_mma, cudaFuncAttributeMaxDynamicSharedMemorySize, SMEM_MMA);

    k_tables<<<(1280 * 64 + 255) / 256, 256>>>(cosT, sinT);
    k_fillcat<<<(TOT * D + 255) / 256, 256>>>(cat, ids, embed, beacon, forget);

    const size_t WDD = (size_t)D * D;
    const size_t WDF = (size_t)D * F;
    const size_t WFD = (size_t)F * D;
    const size_t MDsz = (size_t)Mm * D;

    for (int l = 0; l < L; l++) {
        const float* mem_l = memory + (size_t)l * MDsz;

        k_outgate<<<(Mm * D + 255) / 256, 256>>>(out + (size_t)l * MDsz, mem_l, cat);
        k_rms<<<TOT, 256>>>(cat, ln1 + (size_t)l * D, x);

        // hidden QKV (batched x3): M=1024, N=1024, K=1024
        {
            GemmArgs ga = {};
            ga.A[0] = x; ga.A[1] = x; ga.A[2] = x;
            ga.B[0] = Wq + l * WDD; ga.B[1] = Wk + l * WDD; ga.B[2] = Wv + l * WDD;
            ga.C[0] = tqkv; ga.C[1] = tqkv + 1048576; ga.C[2] = tqkv + 2097152;
            k_mma<<<dim3(8, 8, 3), 256, SMEM_MMA>>>(ga, D, D, 0);
        }
        // eight 128-row projections (batched x8): M=128, N=1024, K=1024
        {
            GemmArgs ga = {};
            const float* bx = x + (size_t)S * D;
            const float* fx = x + (size_t)(S + Mm) * D;
            ga.A[0] = mem_l; ga.A[1] = mem_l;
            ga.A[2] = bx; ga.A[3] = bx; ga.A[4] = bx;
            ga.A[5] = fx; ga.A[6] = fx; ga.A[7] = fx;
            ga.B[0] = mWk + l * WDD; ga.B[1] = mWv + l * WDD;
            ga.B[2] = bWq + l * WDD; ga.B[3] = bWk + l * WDD; ga.B[4] = bWv + l * WDD;
            ga.B[5] = fWq + l * WDD; ga.B[6] = fWk + l * WDD; ga.B[7] = fWv + l * WDD;
            for (int z = 0; z < 8; z++) ga.C[z] = tsm + (size_t)z * 131072;
            k_mma<<<dim3(8, 1, 8), 256, SMEM_MMA>>>(ga, D, D, 0);
        }
        // rope + reshape (batched x11)
        {
            RsArgs ra;
            ra.e[0]  = { tqkv,            qh,     S,  1024, 0,    Mm };
            ra.e[1]  = { tqkv + 1048576,  kbuf,   S,  1280, 128,  Mm };
            ra.e[2]  = { tqkv + 2097152,  vbuf,   S,  1280, 128,  -1 };
            ra.e[3]  = { tsm,             kbuf,   Mm, 1280, 0,    0  };
            ra.e[4]  = { tsm + 131072,    vbuf,   Mm, 1280, 0,    -1 };
            ra.e[5]  = { tsm + 262144,    qbuf_b, Mm, 128,  0,    KHID };
            ra.e[6]  = { tsm + 393216,    kbuf,   Mm, 1280, KHID, KHID };
            ra.e[7]  = { tsm + 524288,    vbuf,   Mm, 1280, KHID, -1 };
            ra.e[8]  = { tsm + 655360,    qbuf_f, Mm, 128,  0,    KHID };
            ra.e[9]  = { tsm + 786432,    kf,     Mm, 128,  0,    KHID };
            ra.e[10] = { tsm + 917504,    vf,     Mm, 128,  0,    -1 };
            k_reshape<<<dim3(4096, 11), 256>>>(ra, cosT, sinT);
        }
        // attention
        k_attn<<<dim3(S / 32, H), 128>>>(qh, S,
                                         kbuf, vbuf, KHID, 1280 * 64,
                                         kf, vf, 0, 128 * 64,
                                         Mm, attn);
        k_attn<<<dim3(Mm / 32, H), 128>>>(qbuf_b, Mm,
                                          kbuf, vbuf, TOT, 1280 * 64,
                                          kf, vf, 0, 128 * 64,
                                          KHID, attn + (size_t)S * D);
        k_attn<<<dim3(Mm / 32, H), 128>>>(qbuf_f, Mm,
                                          kbuf, vbuf, KHID, 1280 * 64,
                                          kf, vf, Mm, 128 * 64,
                                          KHID, attn + (size_t)KHID * D);
        // Wo projection (+residual): M=1280, N=1024, K=1024
        {
            GemmArgs ga = {};
            ga.A[0] = attn; ga.B[0] = Wo + l * WDD; ga.C[0] = cat;
            k_mma<<<dim3(8, 10, 1), 256, SMEM_MMA>>>(ga, D, D, 1);
        }
        k_rms<<<TOT, 256>>>(cat, ln2 + (size_t)l * D, y);
        // MLP gate & up (batched x2): M=1280, N=2048, K=1024
        {
            GemmArgs ga = {};
            ga.A[0] = y; ga.A[1] = y;
            ga.B[0] = Wg + l * WDF; ga.B[1] = Wu + l * WDF;
            ga.C[0] = tg; ga.C[1] = tu;
            k_mma<<<dim3(16, 10, 2), 256, SMEM_MMA>>>(ga, F, D, 0);
        }
        k_silu<<<(TOT * F + 255) / 256, 256>>>(tg, tu);
        // down projection (+residual): M=1280, N=1024, K=2048
        {
            GemmArgs ga = {};
            ga.A[0] = tg; ga.B[0] = Wd + l * WFD; ga.C[0] = cat;
            k_mma<<<dim3(8, 10, 1), 256, SMEM_MMA>>>(ga, D, F, 1);
        }
    }
}

// round 5
// speedup vs baseline: 1.4808x; 1.0872x over previous
#include <cuda_runtime.h>
#include <cuda_bf16.h>
#include <math.h>

// Problem constants
constexpr int S  = 1024;
constexpr int Mm = 128;
constexpr int D  = 1024;
constexpr int H  = 16;
constexpr int HD = 64;
constexpr int F  = 2048;
constexpr int L  = 8;
constexpr int TOT = S + 2 * Mm;     // 1280
constexpr int KHID = Mm + S;        // 1152

// ---------------- f32 scratch pool ----------------
constexpr size_t OFF_CAT  = 0;                          // 1280*1024
constexpr size_t OFF_Q    = 5242880;                    // 16*1024*64
constexpr size_t OFF_QB   = 6291456;
constexpr size_t OFF_QF   = 6422528;
constexpr size_t OFF_K    = 6553600;                    // 16*1280*64
constexpr size_t OFF_V    = 7864320;
constexpr size_t OFF_KF   = 9175040;
constexpr size_t OFF_VF   = 9306112;
constexpr size_t OFF_TQKV = 9437184;                    // 3*1024*1024
constexpr size_t OFF_TSM  = 12582912;                   // 8*128*1024
constexpr size_t OFF_TG   = 13631488;                   // 1280*2048
constexpr size_t OFF_TU   = 16252928;                   // 1280*2048
constexpr size_t OFF_COS  = 18874368;
constexpr size_t OFF_SIN  = 18956288;
constexpr size_t POOL_SZ  = 19038208;
__device__ __align__(16) float g_pool[POOL_SZ];

// ---------------- bf16 scratch pool ----------------
constexpr size_t BW_DXD   = 0;                   // i-th DxD: hi at i*2097152, lo +1048576
constexpr size_t BW_WG    = 25165824;            // hi, lo +2097152
constexpr size_t BW_WU    = 29360128;
constexpr size_t BW_WD    = 33554432;
constexpr size_t B_XH     = 37748736;            // 1280*1024
constexpr size_t B_XL     = 39059456;
constexpr size_t B_AH     = 40370176;
constexpr size_t B_AL     = 41680896;
constexpr size_t B_YH     = 42991616;
constexpr size_t B_YL     = 44302336;
constexpr size_t B_GH     = 45613056;            // 1280*2048
constexpr size_t B_GL     = 48234496;
constexpr size_t B_MEH    = 50855936;            // 128*1024
constexpr size_t B_MEL    = 50987008;
constexpr size_t BPOOL_SZ = 51118080;
__device__ __align__(16) __nv_bfloat16 g_poolbf[BPOOL_SZ];

// ---------------- rope tables ----------------
__global__ void k_tables(float* cosT, float* sinT) {
    int idx = blockIdx.x * blockDim.x + threadIdx.x;
    if (idx >= 1280 * 64) return;
    int p = idx >> 6;
    int d = idx & 63;
    int i = d & 31;
    double inv = pow(10000.0, -((double)i) / 32.0);
    double ang = (double)p * inv;
    cosT[idx] = (float)cos(ang);
    sinT[idx] = (float)sin(ang);
}

// ---------------- initial residual ----------------
__global__ void k_fillcat(float* cat, const int* __restrict__ ids,
                          const float* __restrict__ embed,
                          const float* __restrict__ beacon,
                          const float* __restrict__ forget) {
    int idx = blockIdx.x * blockDim.x + threadIdx.x;
    if (idx >= TOT * D) return;
    int row = idx >> 10;
    int d = idx & 1023;
    float v;
    if (row < S)            v = embed[(size_t)ids[row] * D + d];
    else if (row < S + Mm)  v = beacon[(size_t)(row - S) * D + d];
    else                    v = forget[(size_t)(row - S - Mm) * D + d];
    cat[idx] = v;
}

// ---------------- gated output ----------------
__global__ void k_outgate(float* __restrict__ out, const float* __restrict__ mem,
                          const float* __restrict__ cat) {
    int idx = blockIdx.x * blockDim.x + threadIdx.x;
    if (idx >= Mm * D) return;
    float bcn = cat[(size_t)S * D + idx];
    float fgt = cat[(size_t)(S + Mm) * D + idx];
    float g = 1.0f / (1.0f + expf(-fgt));
    out[idx] = mem[idx] * g + bcn * (1.0f - g);
}

// ---------------- rmsnorm -> bf16 hi/lo ----------------
__global__ void k_rms(const float* __restrict__ in, const float* __restrict__ w,
                      __nv_bfloat16* __restrict__ oh, __nv_bfloat16* __restrict__ ol) {
    int row = blockIdx.x;
    const float* r = in + (size_t)row * D;
    float ss = 0.0f;
    for (int i = threadIdx.x; i < D; i += 256) { float v = r[i]; ss = fmaf(v, v, ss); }
    #pragma unroll
    for (int o = 16; o; o >>= 1) ss += __shfl_xor_sync(0xffffffffu, ss, o);
    __shared__ float wsum[8];
    __shared__ float sc;
    if ((threadIdx.x & 31) == 0) wsum[threadIdx.x >> 5] = ss;
    __syncthreads();
    if (threadIdx.x == 0) {
        float tot = 0.0f;
        #pragma unroll
        for (int i = 0; i < 8; i++) tot += wsum[i];
        sc = rsqrtf(tot / (float)D + 1e-5f);
    }
    __syncthreads();
    float scale = sc;
    size_t base = (size_t)row * D;
    for (int i = threadIdx.x; i < D; i += 256) {
        float v = r[i] * scale * w[i];
        __nv_bfloat16 h = __float2bfloat16(v);
        oh[base + i] = h;
        ol[base + i] = __float2bfloat16(v - __bfloat162float(h));
    }
}

// ---------------- weight transpose + hi/lo split ----------------
struct WcEnt { const float* src; __nv_bfloat16* dh; __nv_bfloat16* dl; int K; int N; int blkOff; };
struct WcArgs { WcEnt e[15]; };

__global__ void __launch_bounds__(256) k_wconv(WcArgs wa) {
    __shared__ float ts[32][33];
    int b = blockIdx.x;
    int ei = 0;
    #pragma unroll
    for (int i = 14; i >= 1; i--) if (b >= wa.e[i].blkOff) { ei = i; break; }
    WcEnt E = wa.e[ei];
    int local = b - E.blkOff;
    int ntx = E.N >> 5;
    int tn = (local % ntx) << 5;
    int tk = (local / ntx) << 5;
    int tx = threadIdx.x & 31, ty = threadIdx.x >> 5;
    #pragma unroll
    for (int j = 0; j < 4; j++)
        ts[ty + j * 8][tx] = E.src[(size_t)(tk + ty + j * 8) * E.N + tn + tx];
    __syncthreads();
    #pragma unroll
    for (int j = 0; j < 4; j++) {
        float v = ts[tx][ty + j * 8];
        __nv_bfloat16 h = __float2bfloat16(v);
        size_t o = (size_t)(tn + ty + j * 8) * E.K + tk + tx;
        E.dh[o] = h;
        E.dl[o] = __float2bfloat16(v - __bfloat162float(h));
    }
}

// ---------------- plain f32 -> bf16 hi/lo split ----------------
__global__ void k_split(const float* __restrict__ src, __nv_bfloat16* __restrict__ dh,
                        __nv_bfloat16* __restrict__ dl, int n) {
    int i = blockIdx.x * 256 + threadIdx.x;
    if (i >= n) return;
    float v = src[i];
    __nv_bfloat16 h = __float2bfloat16(v);
    dh[i] = h;
    dl[i] = __float2bfloat16(v - __bfloat162float(h));
}

// =======================================================================
// HMMA GEMM: C[z] = A[z] @ B[z]^T (+C).  A:[M][K] bf16 hi/lo, B:[N][K]
// bf16 hi/lo (pre-transposed).  3-pass split: AhBh + AhBl + AlBh.
// CTA tile 128x128, BK=64, 2-stage cp.async pipeline, 8 warps (64x32 each).
// smem per stage: Ah 16K | Al 16K | Bh 16K | Bl 16K  = 64KB; 2 stages.
// =======================================================================
struct GArgs {
    const __nv_bfloat16* Ah[11]; const __nv_bfloat16* Al[11];
    const __nv_bfloat16* Bh[11]; const __nv_bfloat16* Bl[11];
    float* C[11];
    int mRows[11];
};

__device__ __forceinline__ void mma16816(float* c, const unsigned* a, const unsigned* b) {
    asm volatile(
        "mma.sync.aligned.m16n8k16.row.col.f32.bf16.bf16.f32 "
        "{%0,%1,%2,%3}, {%4,%5,%6,%7}, {%8,%9}, {%0,%1,%2,%3};"
        : "+f"(c[0]), "+f"(c[1]), "+f"(c[2]), "+f"(c[3])
        : "r"(a[0]), "r"(a[1]), "r"(a[2]), "r"(a[3]), "r"(b[0]), "r"(b[1]));
}
__device__ __forceinline__ void ldsm4(unsigned* r, unsigned addr) {
    asm volatile("ldmatrix.sync.aligned.m8n8.x4.shared.b16 {%0,%1,%2,%3}, [%4];"
                 : "=r"(r[0]), "=r"(r[1]), "=r"(r[2]), "=r"(r[3]) : "r"(addr));
}
__device__ __forceinline__ void cpasync16(unsigned saddr, const void* gptr) {
    asm volatile("cp.async.cg.shared.global [%0], [%1], 16;"
                 :: "r"(saddr), "l"(gptr) : "memory");
}
__device__ __forceinline__ void cp_commit() {
    asm volatile("cp.async.commit_group;" ::: "memory");
}
template<int NN> __device__ __forceinline__ void cp_wait() {
    asm volatile("cp.async.wait_group %0;" :: "n"(NN) : "memory");
}

__global__ void __launch_bounds__(256, 1) k_hmma(GArgs ga, int N, int K, int accFlag) {
    extern __shared__ __align__(128) char smraw[];
    const int z = blockIdx.z;
    const int mbase = blockIdx.y << 7;
    if (mbase >= ga.mRows[z]) return;
    const int nbase = blockIdx.x << 7;

    const __nv_bfloat16* Ah = ga.Ah[z];
    const __nv_bfloat16* Al = ga.Al[z];
    const __nv_bfloat16* Bh = ga.Bh[z];
    const __nv_bfloat16* Bl = ga.Bl[z];
    float* C = ga.C[z];

    const int t = threadIdx.x;
    const int l = t & 31;
    const int w = t >> 5;
    const int wr = w >> 2;          // 0..1 -> 64 M rows
    const int wc = w & 3;           // 0..3 -> 32 N cols
    const unsigned sb = (unsigned)__cvta_generic_to_shared(smraw);

    // loader: 4 chunks per array per thread (16B each)
    const int ldrow = t >> 3;       // wait: need 4 iterations i -> id = t + i*256
    (void)ldrow;
    auto load_stage = [&](int c, int s) {
        unsigned stg = sb + (unsigned)s * 65536u;
        int k0 = c << 6;
        #pragma unroll
        for (int i = 0; i < 4; i++) {
            int id = t + i * 256;
            int row = id >> 3, kc = id & 7;
            unsigned soff = stg + (unsigned)row * 128u + (unsigned)((kc ^ (row & 7)) << 4);
            size_t ao = (size_t)(mbase + row) * K + k0 + kc * 8;
            size_t bo = (size_t)(nbase + row) * K + k0 + kc * 8;
            cpasync16(soff,          Ah + ao);
            cpasync16(soff + 16384u, Al + ao);
            cpasync16(soff + 32768u, Bh + bo);
            cpasync16(soff + 49152u, Bl + bo);
        }
        cp_commit();
    };

    float acc[4][4][4];
    #pragma unroll
    for (int i = 0; i < 4; i++)
        #pragma unroll
        for (int j = 0; j < 4; j++)
            #pragma unroll
            for (int q = 0; q < 4; q++) acc[i][j][q] = 0.0f;

    const int nc = K >> 6;
    load_stage(0, 0);
    if (nc > 1) load_stage(1, 1);

    for (int c = 0; c < nc; c++) {
        if (c + 1 < nc) cp_wait<1>(); else cp_wait<0>();
        __syncthreads();
        unsigned stg = sb + (unsigned)(c & 1) * 65536u;
        #pragma unroll
        for (int ks = 0; ks < 4; ks++) {
            unsigned aH[4][4], aL[4][4], bH[2][4], bL[2][4];
            #pragma unroll
            for (int mt = 0; mt < 4; mt++) {
                int row = wr * 64 + mt * 16 + (l & 15);
                int chunk = ks * 2 + (l >> 4);
                unsigned off = stg + (unsigned)row * 128u + (unsigned)((chunk ^ (row & 7)) << 4);
                ldsm4(aH[mt], off);
                ldsm4(aL[mt], off + 16384u);
            }
            #pragma unroll
            for (int p = 0; p < 2; p++) {
                int nrow = wc * 32 + p * 16 + ((l >> 1) & 8) + (l & 7);
                int chunk = ks * 2 + ((l >> 3) & 1);
                unsigned off = stg + 32768u + (unsigned)nrow * 128u +
                               (unsigned)((chunk ^ (nrow & 7)) << 4);
                ldsm4(bH[p], off);
                ldsm4(bL[p], off + 16384u);
            }
            #pragma unroll
            for (int mt = 0; mt < 4; mt++)
                #pragma unroll
                for (int j = 0; j < 4; j++) {
                    const unsigned* bh = &bH[j >> 1][(j & 1) * 2];
                    const unsigned* bl = &bL[j >> 1][(j & 1) * 2];
                    mma16816(acc[mt][j], aH[mt], bh);
                    mma16816(acc[mt][j], aH[mt], bl);
                    mma16816(acc[mt][j], aL[mt], bh);
                }
        }
        __syncthreads();
        if (c + 2 < nc) load_stage(c + 2, c & 1);
    }

    // epilogue
    int r0 = wr * 64 + (l >> 2);
    int c0 = wc * 32 + (l & 3) * 2;
    #pragma unroll
    for (int mt = 0; mt < 4; mt++) {
        #pragma unroll
        for (int j = 0; j < 4; j++) {
            int row = mbase + r0 + mt * 16;
            int col = nbase + c0 + j * 8;
            float2 v01 = { acc[mt][j][0], acc[mt][j][1] };
            float2 v23 = { acc[mt][j][2], acc[mt][j][3] };
            float* p0 = C + (size_t)row * N + col;
            float* p1 = C + (size_t)(row + 8) * N + col;
            if (accFlag) {
                float2 o0 = *(const float2*)p0;
                float2 o1 = *(const float2*)p1;
                v01.x += o0.x; v01.y += o0.y;
                v23.x += o1.x; v23.y += o1.y;
            }
            *(float2*)p0 = v01;
            *(float2*)p1 = v23;
        }
    }
}

// ---------------- rope + head-major reshape ----------------
struct RsOne {
    const float* src;
    float*       dst;
    int rows;
    int dstStride;
    int dstOff;
    int posBase;
};
struct RsArgs { RsOne e[11]; };

__global__ void k_reshape(RsArgs ra, const float* __restrict__ cosT,
                          const float* __restrict__ sinT) {
    RsOne a = ra.e[blockIdx.y];
    int idx = blockIdx.x * 256 + threadIdx.x;
    if (idx >= a.rows * 1024) return;
    int row = idx >> 10;
    int n = idx & 1023;
    int h = n >> 6;
    int d = n & 63;
    float v = a.src[idx];
    float o;
    if (a.posBase >= 0) {
        int pos = a.posBase + row;
        float partner = (d < 32)
            ? -a.src[(size_t)row * 1024 + h * 64 + d + 32]
            :  a.src[(size_t)row * 1024 + h * 64 + d - 32];
        o = v * cosT[pos * 64 + d] + partner * sinT[pos * 64 + d];
    } else {
        o = v;
    }
    a.dst[((size_t)h * a.dstStride + a.dstOff + row) * 64 + d] = o;
}

// ---------------- flash-style attention -> bf16 hi/lo out ----------------
__global__ void __launch_bounds__(128) k_attn(
    const float* __restrict__ Q, int nq,
    const float* __restrict__ K1, const float* __restrict__ V1, int len1, int hs1,
    const float* __restrict__ K2, const float* __restrict__ V2, int len2, int hs2,
    int P, __nv_bfloat16* __restrict__ OutH, __nv_bfloat16* __restrict__ OutL)
{
    constexpr int TQ = 32, TK = 32;
    int h  = blockIdx.y;
    int qb = blockIdx.x * TQ;
    int t  = threadIdx.x;
    int r  = t >> 2;
    int c4 = t & 3;
    int d0 = c4 * 16;

    __shared__ __align__(16) float Ks[TK][64];
    __shared__ __align__(16) float Vs[TK][64];

    const float* Qh = Q + (size_t)h * nq * 64;

    float qreg[16];
    #pragma unroll
    for (int i = 0; i < 16; i += 4) {
        float4 v = *(const float4*)(Qh + (size_t)(qb + r) * 64 + d0 + i);
        qreg[i + 0] = v.x * 0.125f;
        qreg[i + 1] = v.y * 0.125f;
        qreg[i + 2] = v.z * 0.125f;
        qreg[i + 3] = v.w * 0.125f;
    }

    float m = -3.0e38f, lsum = 0.0f;
    float O[16];
    #pragma unroll
    for (int i = 0; i < 16; i++) O[i] = 0.0f;

    int total = len1 + len2;
    int eff = min(total, P + qb + TQ);
    int ntk = (eff + TK - 1) / TK;
    int qi = qb + r;

    for (int kt = 0; kt < ntk; kt++) {
        int j = kt * TK + r;
        const float *kp, *vp;
        if (j < len1) {
            kp = K1 + (size_t)h * hs1 + (size_t)j * 64;
            vp = V1 + (size_t)h * hs1 + (size_t)j * 64;
        } else {
            kp = K2 + (size_t)h * hs2 + (size_t)(j - len1) * 64;
            vp = V2 + (size_t)h * hs2 + (size_t)(j - len1) * 64;
        }
        __syncthreads();
        #pragma unroll
        for (int i = 0; i < 16; i += 4) {
            *(float4*)(&Ks[r][d0 + i]) = *(const float4*)(kp + d0 + i);
            *(float4*)(&Vs[r][d0 + i]) = *(const float4*)(vp + d0 + i);
        }
        __syncthreads();

        float s[TK];
        #pragma unroll
        for (int k = 0; k < TK; k++) {
            const float4* kp4 = (const float4*)(&Ks[k][d0]);
            float a = 0.0f;
            #pragma unroll
            for (int i4 = 0; i4 < 4; i4++) {
                float4 kv = kp4[i4];
                a = fmaf(qreg[i4 * 4 + 0], kv.x, a);
                a = fmaf(qreg[i4 * 4 + 1], kv.y, a);
                a = fmaf(qreg[i4 * 4 + 2], kv.z, a);
                a = fmaf(qreg[i4 * 4 + 3], kv.w, a);
            }
            s[k] = a;
        }
        #pragma unroll
        for (int k = 0; k < TK; k++) {
            s[k] += __shfl_xor_sync(0xffffffffu, s[k], 1);
            s[k] += __shfl_xor_sync(0xffffffffu, s[k], 2);
        }
        int jg0 = kt * TK;
        #pragma unroll
        for (int k = 0; k < TK; k++) {
            int jg = jg0 + k;
            bool vis = (jg < P) || (jg - P <= qi);
            if (!vis) s[k] = -3.0e38f;
        }
        float tmax = s[0];
        #pragma unroll
        for (int k = 1; k < TK; k++) tmax = fmaxf(tmax, s[k]);
        float nm = fmaxf(m, tmax);
        float corr = __expf(m - nm);
        lsum *= corr;
        #pragma unroll
        for (int i = 0; i < 16; i++) O[i] *= corr;
        #pragma unroll
        for (int k = 0; k < TK; k++) {
            float p = __expf(s[k] - nm);
            lsum += p;
            const float4* vp4 = (const float4*)(&Vs[k][d0]);
            #pragma unroll
            for (int i4 = 0; i4 < 4; i4++) {
                float4 vv = vp4[i4];
                O[i4 * 4 + 0] = fmaf(p, vv.x, O[i4 * 4 + 0]);
                O[i4 * 4 + 1] = fmaf(p, vv.y, O[i4 * 4 + 1]);
                O[i4 * 4 + 2] = fmaf(p, vv.z, O[i4 * 4 + 2]);
                O[i4 * 4 + 3] = fmaf(p, vv.w, O[i4 * 4 + 3]);
            }
        }
        m = nm;
    }

    float inv = 1.0f / lsum;
    size_t base = (size_t)(qb + r) * 1024 + h * 64 + d0;
    #pragma unroll
    for (int i = 0; i < 16; i++) {
        float v = O[i] * inv;
        __nv_bfloat16 hh = __float2bfloat16(v);
        OutH[base + i] = hh;
        OutL[base + i] = __float2bfloat16(v - __bfloat162float(hh));
    }
}

// ---------------- MLP activation -> bf16 hi/lo ----------------
__global__ void k_silu(const float* __restrict__ g, const float* __restrict__ u,
                       __nv_bfloat16* __restrict__ oh, __nv_bfloat16* __restrict__ ol) {
    int idx = blockIdx.x * blockDim.x + threadIdx.x;
    if (idx >= TOT * F) return;
    float x = g[idx];
    float s = x / (1.0f + expf(-x));
    float v = s * u[idx];
    __nv_bfloat16 h = __float2bfloat16(v);
    oh[idx] = h;
    ol[idx] = __float2bfloat16(v - __bfloat162float(h));
}

// ---------------- host driver ----------------
extern "C" void kernel_launch(void* const* d_in, const int* in_sizes, int n_in,
                              void* d_out, int out_size) {
    (void)in_sizes; (void)n_in; (void)out_size;

    const int*   ids    = (const int*)  d_in[0];
    const float* memory = (const float*)d_in[1];
    const float* beacon = (const float*)d_in[2];
    const float* forget = (const float*)d_in[3];
    const float* embed  = (const float*)d_in[4];
    const float* ln1    = (const float*)d_in[5];
    const float* ln2    = (const float*)d_in[6];
    const float* Wsrc[12] = {
        (const float*)d_in[7],  (const float*)d_in[8],  (const float*)d_in[9],
        (const float*)d_in[10], (const float*)d_in[11], (const float*)d_in[12],
        (const float*)d_in[13], (const float*)d_in[14], (const float*)d_in[15],
        (const float*)d_in[16], (const float*)d_in[17], (const float*)d_in[18]
    }; // Wq Wk Wv Wo mWk mWv bWq bWk bWv fWq fWk fWv
    const float* Wg = (const float*)d_in[19];
    const float* Wu = (const float*)d_in[20];
    const float* Wd = (const float*)d_in[21];
    float* out = (float*)d_out;

    float* pool = nullptr;
    cudaGetSymbolAddress((void**)&pool, g_pool);
    __nv_bfloat16* bp = nullptr;
    cudaGetSymbolAddress((void**)&bp, g_poolbf);

    float* cat  = pool + OFF_CAT;
    float* qh_f = pool + OFF_Q;
    float* qbuf_b = pool + OFF_QB;
    float* qbuf_f = pool + OFF_QF;
    float* kbuf = pool + OFF_K;
    float* vbuf = pool + OFF_V;
    float* kf   = pool + OFF_KF;
    float* vf   = pool + OFF_VF;
    float* tqkv = pool + OFF_TQKV;
    float* tsm  = pool + OFF_TSM;
    float* tg   = pool + OFF_TG;
    float* tu   = pool + OFF_TU;
    float* cosT = pool + OFF_COS;
    float* sinT = pool + OFF_SIN;

    __nv_bfloat16* xh = bp + B_XH;  __nv_bfloat16* xl = bp + B_XL;
    __nv_bfloat16* ah = bp + B_AH;  __nv_bfloat16* al = bp + B_AL;
    __nv_bfloat16* yh = bp + B_YH;  __nv_bfloat16* yl = bp + B_YL;
    __nv_bfloat16* gh = bp + B_GH;  __nv_bfloat16* gl = bp + B_GL;
    __nv_bfloat16* meh = bp + B_MEH; __nv_bfloat16* mel = bp + B_MEL;

    constexpr int SMEM_HM = 131072;
    cudaFuncSetAttribute(k_hmma, cudaFuncAttributeMaxDynamicSharedMemorySize, SMEM_HM);

    k_tables<<<(1280 * 64 + 255) / 256, 256>>>(cosT, sinT);
    k_fillcat<<<(TOT * D + 255) / 256, 256>>>(cat, ids, embed, beacon, forget);

    const size_t WDD = (size_t)D * D;
    const size_t WDF = (size_t)D * F;
    const size_t WFD = (size_t)F * D;
    const size_t MDsz = (size_t)Mm * D;

    __nv_bfloat16* wtH[15]; __nv_bfloat16* wtL[15];
    for (int i = 0; i < 12; i++) {
        wtH[i] = bp + BW_DXD + (size_t)i * 2097152;
        wtL[i] = wtH[i] + 1048576;
    }
    wtH[12] = bp + BW_WG; wtL[12] = wtH[12] + 2097152;
    wtH[13] = bp + BW_WU; wtL[13] = wtH[13] + 2097152;
    wtH[14] = bp + BW_WD; wtL[14] = wtH[14] + 2097152;

    for (int l = 0; l < L; l++) {
        const float* mem_l = memory + (size_t)l * MDsz;

        // weight conversion for this layer (transpose to [N][K] + hi/lo split)
        {
            WcArgs wa;
            int off = 0;
            for (int i = 0; i < 12; i++) {
                wa.e[i] = { Wsrc[i] + (size_t)l * WDD, wtH[i], wtL[i], D, D, off };
                off += (D / 32) * (D / 32);
            }
            wa.e[12] = { Wg + (size_t)l * WDF, wtH[12], wtL[12], D, F, off }; off += (D/32)*(F/32);
            wa.e[13] = { Wu + (size_t)l * WDF, wtH[13], wtL[13], D, F, off }; off += (D/32)*(F/32);
            wa.e[14] = { Wd + (size_t)l * WFD, wtH[14], wtL[14], F, D, off }; off += (F/32)*(D/32);
            k_wconv<<<off, 256>>>(wa);
        }
        k_split<<<(Mm * D + 255) / 256, 256>>>(mem_l, meh, mel, Mm * D);

        k_outgate<<<(Mm * D + 255) / 256, 256>>>(out + (size_t)l * MDsz, mem_l, cat);
        k_rms<<<TOT, 256>>>(cat, ln1 + (size_t)l * D, xh, xl);

        // merged: hidden QKV (z0-2, M=1024) + eight 128-row projections (z3-10)
        {
            GArgs ga = {};
            for (int z = 0; z < 3; z++) {
                ga.Ah[z] = xh; ga.Al[z] = xl;
                ga.Bh[z] = wtH[z]; ga.Bl[z] = wtL[z];
                ga.C[z] = tqkv + (size_t)z * 1048576;
                ga.mRows[z] = S;
            }
            const __nv_bfloat16* bxh = xh + (size_t)S * D;
            const __nv_bfloat16* bxl = xl + (size_t)S * D;
            const __nv_bfloat16* fxh = xh + (size_t)(S + Mm) * D;
            const __nv_bfloat16* fxl = xl + (size_t)(S + Mm) * D;
            const __nv_bfloat16* sAh[8] = { meh, meh, bxh, bxh, bxh, fxh, fxh, fxh };
            const __nv_bfloat16* sAl[8] = { mel, mel, bxl, bxl, bxl, fxl, fxl, fxl };
            int wmap[8] = {4, 5, 6, 7, 8, 9, 10, 11}; // mWk mWv bWq bWk bWv fWq fWk fWv
            for (int z = 0; z < 8; z++) {
                ga.Ah[3 + z] = sAh[z]; ga.Al[3 + z] = sAl[z];
                ga.Bh[3 + z] = wtH[wmap[z]]; ga.Bl[3 + z] = wtL[wmap[z]];
                ga.C[3 + z] = tsm + (size_t)z * 131072;
                ga.mRows[3 + z] = Mm;
            }
            k_hmma<<<dim3(8, 8, 11), 256, SMEM_HM>>>(ga, D, D, 0);
        }
        // rope + reshape
        {
            RsArgs ra;
            ra.e[0]  = { tqkv,            qh_f,   S,  1024, 0,    Mm };
            ra.e[1]  = { tqkv + 1048576,  kbuf,   S,  1280, 128,  Mm };
            ra.e[2]  = { tqkv + 2097152,  vbuf,   S,  1280, 128,  -1 };
            ra.e[3]  = { tsm,             kbuf,   Mm, 1280, 0,    0  };
            ra.e[4]  = { tsm + 131072,    vbuf,   Mm, 1280, 0,    -1 };
            ra.e[5]  = { tsm + 262144,    qbuf_b, Mm, 128,  0,    KHID };
            ra.e[6]  = { tsm + 393216,    kbuf,   Mm, 1280, KHID, KHID };
            ra.e[7]  = { tsm + 524288,    vbuf,   Mm, 1280, KHID, -1 };
            ra.e[8]  = { tsm + 655360,    qbuf_f, Mm, 128,  0,    KHID };
            ra.e[9]  = { tsm + 786432,    kf,     Mm, 128,  0,    KHID };
            ra.e[10] = { tsm + 917504,    vf,     Mm, 128,  0,    -1 };
            k_reshape<<<dim3(4096, 11), 256>>>(ra, cosT, sinT);
        }
        // attention (writes bf16 hi/lo into ah/al)
        k_attn<<<dim3(S / 32, H), 128>>>(qh_f, S,
                                         kbuf, vbuf, KHID, 1280 * 64,
                                         kf, vf, 0, 128 * 64,
                                         Mm, ah, al);
        k_attn<<<dim3(Mm / 32, H), 128>>>(qbuf_b, Mm,
                                          kbuf, vbuf, TOT, 1280 * 64,
                                          kf, vf, 0, 128 * 64,
                                          KHID, ah + (size_t)S * D, al + (size_t)S * D);
        k_attn<<<dim3(Mm / 32, H), 128>>>(qbuf_f, Mm,
                                          kbuf, vbuf, KHID, 1280 * 64,
                                          kf, vf, Mm, 128 * 64,
                                          KHID, ah + (size_t)KHID * D, al + (size_t)KHID * D);
        // Wo (+residual): M=1280, N=1024, K=1024
        {
            GArgs ga = {};
            ga.Ah[0] = ah; ga.Al[0] = al;
            ga.Bh[0] = wtH[3]; ga.Bl[0] = wtL[3];
            ga.C[0] = cat;
            ga.mRows[0] = TOT;
            k_hmma<<<dim3(8, 10, 1), 256, SMEM_HM>>>(ga, D, D, 1);
        }
        k_rms<<<TOT, 256>>>(cat, ln2 + (size_t)l * D, yh, yl);
        // MLP gate & up: M=1280, N=2048, K=1024
        {
            GArgs ga = {};
            ga.Ah[0] = yh; ga.Al[0] = yl; ga.Ah[1] = yh; ga.Al[1] = yl;
            ga.Bh[0] = wtH[12]; ga.Bl[0] = wtL[12];
            ga.Bh[1] = wtH[13]; ga.Bl[1] = wtL[13];
            ga.C[0] = tg; ga.C[1] = tu;
            ga.mRows[0] = TOT; ga.mRows[1] = TOT;
            k_hmma<<<dim3(16, 10, 2), 256, SMEM_HM>>>(ga, F, D, 0);
        }
        k_silu<<<(TOT * F + 255) / 256, 256>>>(tg, tu, gh, gl);
        // down (+residual): M=1280, N=1024, K=2048
        {
            GArgs ga = {};
            ga.Ah[0] = gh; ga.Al[0] = gl;
            ga.Bh[0] = wtH[14]; ga.Bl[0] = wtL[14];
            ga.C[0] = cat;
            ga.mRows[0] = TOT;
            k_hmma<<<dim3(8, 10, 1), 256, SMEM_HM>>>(ga, D, F, 1);
        }
    }
}